// round 2
// baseline (speedup 1.0000x reference)
#include <cuda_runtime.h>

#define BB   32
#define NN   2048
#define KK   16
#define FIN  32
#define FOUT 64
#define NPTS (BB * NN)          // 65536
#define PAD  4
#define NS   (NN + 2 * PAD)     // 2056

// Scratch (allocation-free rule: __device__ globals)
__device__ float4 g_sorted[BB * NS];   // per batch: x-sorted (x,y,z, localIdx-bits) + sentinels
__device__ float  g_a[NPTS * FOUT];    // x @ (W1 - W2) + b_edge
__device__ float  g_c[NPTS * FOUT];    // x @ W2
__device__ float  g_s[NPTS * FOUT];    // relu(x @ W_nn + b_nn)
__device__ int    g_idx[NPTS * KK];    // global neighbor indices

// ---------------------------------------------------------------------------
// Kernel 0: per-batch bitonic sort of points by x (key), carrying (y,z,idx).
// One 1024-thread block per batch; 2048 elements in SMEM.
// ---------------------------------------------------------------------------
__global__ __launch_bounds__(1024) void sort_kernel(const float* __restrict__ pos) {
    __shared__ float4 sm[NN];
    const int b   = blockIdx.x;
    const int tid = threadIdx.x;

    for (int i = tid; i < NN; i += 1024) {
        const float* p = pos + (size_t)(b * NN + i) * 3;
        sm[i] = make_float4(p[0], p[1], p[2], __int_as_float(i));
    }

    for (int k = 2; k <= NN; k <<= 1) {
        for (int j = k >> 1; j > 0; j >>= 1) {
            __syncthreads();
            int l = ((tid & ~(j - 1)) << 1) | (tid & (j - 1));
            int p = l | j;
            float4 A = sm[l];
            float4 Bv = sm[p];
            bool asc = (l & k) == 0;
            if ((A.x > Bv.x) == asc) { sm[l] = Bv; sm[p] = A; }
        }
    }
    __syncthreads();

    float4* gs = g_sorted + (size_t)b * NS;
    for (int i = tid; i < NN; i += 1024) gs[PAD + i] = sm[i];
    if (tid < PAD) {
        gs[tid]            = make_float4(-1.0e30f, 0.f, 0.f, __int_as_float(0));
        gs[PAD + NN + tid] = make_float4( 1.0e30f, 0.f, 0.f, __int_as_float(0));
    }
}

// ---------------------------------------------------------------------------
// Kernel 1: kNN via sorted-x sweep with (dx)^2 lower-bound cutoff.
// Pass 1: values-only top-16 -> threshold tau. Pass 2: emit indices d2 <= tau.
// 256 threads/block, 8 blocks per batch. Thread = sorted rank (warp-coherent
// windows). Exact selection (cutoff is a valid lower bound on d2).
// ---------------------------------------------------------------------------
__global__ __launch_bounds__(256) void knn_kernel() {
    __shared__ float4 sp[NS];   // 32.9 KB

    const int b    = blockIdx.x >> 3;
    const int part = blockIdx.x & 7;
    const int tid  = threadIdx.x;

    const float4* gs = g_sorted + (size_t)b * NS;
    for (int i = tid; i < NS; i += 256) sp[i] = gs[i];
    __syncthreads();

    const int rank = (part << 8) + tid;
    const float4* ctr = sp + PAD + rank;
    const float4 me = ctr[0];

    // ---- Pass 1: threshold via values-only sorted top-16 ----
    float dk[KK];
#pragma unroll
    for (int k = 0; k < KK; k++) dk[k] = 3.0e38f;

    bool gl = true, gr = true;
    for (int s = 1; gl || gr; s++) {
        if (gl) {
            float4 q = ctr[-s];
            float dx = me.x - q.x;
            float dxx = dx * dx;
            if (dxx > dk[KK - 1]) gl = false;
            else {
                float dy = me.y - q.y;
                float dz = me.z - q.z;
                float d2 = fmaf(dy, dy, fmaf(dz, dz, dxx));
                if (d2 < dk[KK - 1]) {
                    float v = d2;
#pragma unroll
                    for (int k = 0; k < KK; k++) {
                        float lo = fminf(dk[k], v);
                        v = fmaxf(dk[k], v);
                        dk[k] = lo;
                    }
                }
            }
        }
        if (gr) {
            float4 q = ctr[s];
            float dx = me.x - q.x;
            float dxx = dx * dx;
            if (dxx > dk[KK - 1]) gr = false;
            else {
                float dy = me.y - q.y;
                float dz = me.z - q.z;
                float d2 = fmaf(dy, dy, fmaf(dz, dz, dxx));
                if (d2 < dk[KK - 1]) {
                    float v = d2;
#pragma unroll
                    for (int k = 0; k < KK; k++) {
                        float lo = fminf(dk[k], v);
                        v = fmaxf(dk[k], v);
                        dk[k] = lo;
                    }
                }
            }
        }
    }
    const float tau = dk[KK - 1];

    // ---- Pass 2: collect indices with d2 <= tau (bit-identical arithmetic) ----
    const int base = b * NN;
    const int qi   = __float_as_int(me.w);
    int* orow = g_idx + (size_t)(base + qi) * KK;

    int cnt = 0;
    int first = base;   // fallback fill (measure-zero path)
    for (int s = 1;; s++) {
        float4 q = ctr[-s];
        float dx = me.x - q.x;
        float dxx = dx * dx;
        if (dxx > tau) break;
        float dy = me.y - q.y;
        float dz = me.z - q.z;
        float d2 = fmaf(dy, dy, fmaf(dz, dz, dxx));
        if (d2 <= tau && cnt < KK) {
            int g = base + __float_as_int(q.w);
            if (cnt == 0) first = g;
            orow[cnt++] = g;
        }
    }
    for (int s = 1;; s++) {
        float4 q = ctr[s];
        float dx = me.x - q.x;
        float dxx = dx * dx;
        if (dxx > tau) break;
        float dy = me.y - q.y;
        float dz = me.z - q.z;
        float d2 = fmaf(dy, dy, fmaf(dz, dz, dxx));
        if (d2 <= tau && cnt < KK) {
            int g = base + __float_as_int(q.w);
            if (cnt == 0) first = g;
            orow[cnt++] = g;
        }
    }
    // Safety fill (only reachable under fp-tie pathologies); duplicate nearest.
    for (; cnt < KK; cnt++) orow[cnt] = first;
}

// ---------------------------------------------------------------------------
// Kernel 2: per-node transforms. a = x@(W1-W2)+b_e, c = x@W2, s = relu(x@Wn+bn)
// Weights in SMEM (all-lane broadcast reads), x row in registers.
// ---------------------------------------------------------------------------
__global__ __launch_bounds__(128) void transform_kernel(
    const float* __restrict__ x,
    const float* __restrict__ We,   // (2*FIN, FOUT)
    const float* __restrict__ be,   // (FOUT)
    const float* __restrict__ Wn,   // (FIN, FOUT)
    const float* __restrict__ bn)   // (FOUT)
{
    __shared__ float s_wd[FIN * FOUT];   // W1 - W2
    __shared__ float s_w2[FIN * FOUT];
    __shared__ float s_wn[FIN * FOUT];
    __shared__ float s_be[FOUT];
    __shared__ float s_bn[FOUT];

    const int tid = threadIdx.x;
    for (int t = tid; t < FIN * FOUT; t += 128) {
        float w2 = We[FIN * FOUT + t];
        s_w2[t] = w2;
        s_wd[t] = We[t] - w2;
        s_wn[t] = Wn[t];
    }
    if (tid < FOUT) { s_be[tid] = be[tid]; s_bn[tid] = bn[tid]; }
    __syncthreads();

    const int node = blockIdx.x * 128 + tid;

    float xr[FIN];
#pragma unroll
    for (int r = 0; r < FIN; r += 4) {
        float4 v = *reinterpret_cast<const float4*>(x + (size_t)node * FIN + r);
        xr[r] = v.x; xr[r + 1] = v.y; xr[r + 2] = v.z; xr[r + 3] = v.w;
    }

    for (int f0 = 0; f0 < FOUT; f0 += 4) {
        float a0 = s_be[f0], a1 = s_be[f0 + 1], a2 = s_be[f0 + 2], a3 = s_be[f0 + 3];
        float c0 = 0.f, c1 = 0.f, c2 = 0.f, c3 = 0.f;
        float k0 = s_bn[f0], k1 = s_bn[f0 + 1], k2 = s_bn[f0 + 2], k3 = s_bn[f0 + 3];
#pragma unroll
        for (int r = 0; r < FIN; r++) {
            float xv = xr[r];
            float4 wd = *reinterpret_cast<const float4*>(&s_wd[r * FOUT + f0]);
            float4 w2 = *reinterpret_cast<const float4*>(&s_w2[r * FOUT + f0]);
            float4 wn = *reinterpret_cast<const float4*>(&s_wn[r * FOUT + f0]);
            a0 = fmaf(xv, wd.x, a0); a1 = fmaf(xv, wd.y, a1);
            a2 = fmaf(xv, wd.z, a2); a3 = fmaf(xv, wd.w, a3);
            c0 = fmaf(xv, w2.x, c0); c1 = fmaf(xv, w2.y, c1);
            c2 = fmaf(xv, w2.z, c2); c3 = fmaf(xv, w2.w, c3);
            k0 = fmaf(xv, wn.x, k0); k1 = fmaf(xv, wn.y, k1);
            k2 = fmaf(xv, wn.z, k2); k3 = fmaf(xv, wn.w, k3);
        }
        size_t o = (size_t)node * FOUT + f0;
        *reinterpret_cast<float4*>(&g_a[o]) = make_float4(a0, a1, a2, a3);
        *reinterpret_cast<float4*>(&g_c[o]) = make_float4(c0, c1, c2, c3);
        *reinterpret_cast<float4*>(&g_s[o]) = make_float4(fmaxf(k0, 0.f), fmaxf(k1, 0.f),
                                                          fmaxf(k2, 0.f), fmaxf(k3, 0.f));
    }
}

// ---------------------------------------------------------------------------
// Kernel 3: aggregation. Thread per (node, feature).
// out = relu(max_k (a_i + c_{nbr_k})) + s_i  ;  relu∘max == max∘relu.
// ---------------------------------------------------------------------------
__global__ __launch_bounds__(256) void aggregate_kernel(float* __restrict__ out) {
    const int gid = blockIdx.x * 256 + threadIdx.x;   // gid == i*FOUT + f
    const int i = gid >> 6;
    const int f = gid & 63;

    int jj[KK];
#pragma unroll
    for (int k = 0; k < KK; k++) jj[k] = g_idx[i * KK + k];   // broadcast loads

    float cv[KK];
#pragma unroll
    for (int k = 0; k < KK; k++) cv[k] = g_c[(size_t)jj[k] * FOUT + f];  // coalesced

    float m = cv[0];
#pragma unroll
    for (int k = 1; k < KK; k++) m = fmaxf(m, cv[k]);

    float af = g_a[gid];
    float sv = g_s[gid];
    out[gid] = fmaxf(m + af, 0.f) + sv;
}

// ---------------------------------------------------------------------------
extern "C" void kernel_launch(void* const* d_in, const int* in_sizes, int n_in,
                              void* d_out, int out_size) {
    const float* x   = (const float*)d_in[0];
    const float* pos = (const float*)d_in[1];
    const float* We  = (const float*)d_in[2];
    const float* be  = (const float*)d_in[3];
    const float* Wn  = (const float*)d_in[4];
    const float* bn  = (const float*)d_in[5];
    float* out = (float*)d_out;

    sort_kernel<<<BB, 1024>>>(pos);
    knn_kernel<<<BB * 8, 256>>>();
    transform_kernel<<<NPTS / 128, 128>>>(x, We, be, Wn, bn);
    aggregate_kernel<<<(NPTS * FOUT) / 256, 256>>>(out);
}

// round 4
// speedup vs baseline: 1.4104x; 1.4104x over previous
#include <cuda_runtime.h>

#define BB   32
#define NN   2048
#define KK   16
#define FIN  32
#define FOUT 64
#define NPTS (BB * NN)          // 65536
#define PAD  4
#define NS   (NN + 2 * PAD)     // 2056

// Scratch (allocation-free rule: __device__ globals)
__device__ float4 g_sorted[BB * NS];   // per batch: x-sorted (x,y,z, idx-bits) + sentinels
__device__ float  g_a[NPTS * FOUT];    // x @ (W1 - W2) + b_edge
__device__ float  g_c[NPTS * FOUT];    // x @ W2
__device__ float  g_s[NPTS * FOUT];    // relu(x @ W_nn + b_nn)
__device__ int    g_idx[NPTS * KK];    // global neighbor indices

// ---------------------------------------------------------------------------
// Kernel 0: per-batch bitonic sort of points by x (key), carrying (y,z,idx).
// ---------------------------------------------------------------------------
__global__ __launch_bounds__(1024) void sort_kernel(const float* __restrict__ pos) {
    __shared__ float4 sm[NN];
    const int b   = blockIdx.x;
    const int tid = threadIdx.x;

    for (int i = tid; i < NN; i += 1024) {
        const float* p = pos + (size_t)(b * NN + i) * 3;
        sm[i] = make_float4(p[0], p[1], p[2], __int_as_float(i));
    }

    for (int k = 2; k <= NN; k <<= 1) {
        for (int j = k >> 1; j > 0; j >>= 1) {
            __syncthreads();
            int l = ((tid & ~(j - 1)) << 1) | (tid & (j - 1));
            int p = l | j;
            float4 A = sm[l];
            float4 Bv = sm[p];
            bool asc = (l & k) == 0;
            if ((A.x > Bv.x) == asc) { sm[l] = Bv; sm[p] = A; }
        }
    }
    __syncthreads();

    float4* gs = g_sorted + (size_t)b * NS;
    for (int i = tid; i < NN; i += 1024) gs[PAD + i] = sm[i];
    if (tid < PAD) {
        gs[tid]            = make_float4(-1.0e30f, 0.f, 0.f, __int_as_float(0));
        gs[PAD + NN + tid] = make_float4( 1.0e30f, 0.f, 0.f, __int_as_float(0));
    }
}

// ---------------------------------------------------------------------------
// Kernel 1: kNN via sorted-x sweep — branch-minimal chunked version.
// Phase 1: two independent values-only top-16 chains (L/R), unconditional
//          inserts, one uniform exit check per 8-step chunk. Merge -> tau.
// Phase 2: re-sweep, emit indices with d2 <= tau (predicated short arm).
// ---------------------------------------------------------------------------
__device__ __forceinline__ void ins16(float dk[KK], float v) {
#pragma unroll
    for (int k = 0; k < KK; k++) {
        float lo = fminf(dk[k], v);
        v = fmaxf(dk[k], v);
        dk[k] = lo;
    }
}

__global__ __launch_bounds__(256) void knn_kernel() {
    __shared__ float4 sp[NS];   // 32.9 KB

    const int b    = blockIdx.x >> 3;
    const int part = blockIdx.x & 7;
    const int tid  = threadIdx.x;

    const float4* gs = g_sorted + (size_t)b * NS;
    for (int i = tid; i < NS; i += 256) sp[i] = gs[i];
    __syncthreads();

    // Interleave warps across the rank space for block load balance;
    // lanes stay contiguous so windows are warp-coherent.
    const int rank = (((tid >> 5) << 3) + part) * 32 + (tid & 31);
    const int ic   = PAD + rank;
    const float4 me = sp[ic];

    float dkL[KK], dkR[KK];
#pragma unroll
    for (int k = 0; k < KK; k++) { dkL[k] = 3.0e38f; dkR[k] = 3.0e38f; }

    // ---- Phase 1 ----
    for (int chunk = 0; chunk < 257; chunk++) {
        float lastL = 0.f, lastR = 0.f;
        const int s0 = chunk << 3;
#pragma unroll
        for (int u = 1; u <= 8; u++) {
            const int s = s0 + u;
            const int jl = max(ic - s, 0);
            const int jr = min(ic + s, NS - 1);
            float4 ql = sp[jl];
            float4 qr = sp[jr];
            float dxl = me.x - ql.x, dyl = me.y - ql.y, dzl = me.z - ql.z;
            float dxr = me.x - qr.x, dyr = me.y - qr.y, dzr = me.z - qr.z;
            float dxl2 = dxl * dxl;
            float dxr2 = dxr * dxr;
            float d2l = fmaf(dyl, dyl, fmaf(dzl, dzl, dxl2));
            float d2r = fmaf(dyr, dyr, fmaf(dzr, dzr, dxr2));
            ins16(dkL, d2l);            // two independent chains (ILP x2)
            ins16(dkR, d2r);
            if (u == 8) { lastL = dxl2; lastR = dxr2; }
        }
        // Sound bound: union's 16th <= min(L's 16th, R's 16th).
        float bound = fminf(dkL[KK - 1], dkR[KK - 1]);
        if (lastL > bound && lastR > bound) break;
    }

    // Exact tau: 16 smallest of (L ∪ R) = { min(L[i], R[15-i]) } (bitonic merge step).
    float tau = 0.f;
#pragma unroll
    for (int i = 0; i < KK; i++)
        tau = fmaxf(tau, fminf(dkL[i], dkR[KK - 1 - i]));

    // ---- Phase 2: collect indices with d2 <= tau ----
    const int base = b * NN;
    const int qi   = __float_as_int(me.w);
    int* orow = g_idx + (size_t)(base + qi) * KK;

    int cnt = 0;
    int first = base;
    for (int chunk = 0; chunk < 257; chunk++) {
        float lastL = 0.f, lastR = 0.f;
        const int s0 = chunk << 3;
#pragma unroll
        for (int u = 1; u <= 8; u++) {
            const int s = s0 + u;
            const int jl = max(ic - s, 0);
            const int jr = min(ic + s, NS - 1);
            float4 ql = sp[jl];
            float4 qr = sp[jr];
            float dxl = me.x - ql.x, dyl = me.y - ql.y, dzl = me.z - ql.z;
            float dxr = me.x - qr.x, dyr = me.y - qr.y, dzr = me.z - qr.z;
            float dxl2 = dxl * dxl;
            float dxr2 = dxr * dxr;
            float d2l = fmaf(dyl, dyl, fmaf(dzl, dzl, dxl2));
            float d2r = fmaf(dyr, dyr, fmaf(dzr, dzr, dxr2));
            if (d2l <= tau && cnt < KK) {
                int g = base + __float_as_int(ql.w);
                if (cnt == 0) first = g;
                orow[cnt++] = g;
            }
            if (d2r <= tau && cnt < KK) {
                int g = base + __float_as_int(qr.w);
                if (cnt == 0) first = g;
                orow[cnt++] = g;
            }
            if (u == 8) { lastL = dxl2; lastR = dxr2; }
        }
        if (lastL > tau && lastR > tau) break;
    }
    for (; cnt < KK; cnt++) orow[cnt] = first;   // measure-zero safety fill
}

// ---------------------------------------------------------------------------
// Kernel 2: per-node transforms. a = x@(W1-W2)+b_e, c = x@W2, s = relu(x@Wn+bn)
// ---------------------------------------------------------------------------
__global__ __launch_bounds__(128) void transform_kernel(
    const float* __restrict__ x,
    const float* __restrict__ We,
    const float* __restrict__ be,
    const float* __restrict__ Wn,
    const float* __restrict__ bn)
{
    __shared__ float s_wd[FIN * FOUT];
    __shared__ float s_w2[FIN * FOUT];
    __shared__ float s_wn[FIN * FOUT];
    __shared__ float s_be[FOUT];
    __shared__ float s_bn[FOUT];

    const int tid = threadIdx.x;
    for (int t = tid; t < FIN * FOUT; t += 128) {
        float w2 = We[FIN * FOUT + t];
        s_w2[t] = w2;
        s_wd[t] = We[t] - w2;
        s_wn[t] = Wn[t];
    }
    if (tid < FOUT) { s_be[tid] = be[tid]; s_bn[tid] = bn[tid]; }
    __syncthreads();

    const int node = blockIdx.x * 128 + tid;

    float xr[FIN];
#pragma unroll
    for (int r = 0; r < FIN; r += 4) {
        float4 v = *reinterpret_cast<const float4*>(x + (size_t)node * FIN + r);
        xr[r] = v.x; xr[r + 1] = v.y; xr[r + 2] = v.z; xr[r + 3] = v.w;
    }

    for (int f0 = 0; f0 < FOUT; f0 += 4) {
        float a0 = s_be[f0], a1 = s_be[f0 + 1], a2 = s_be[f0 + 2], a3 = s_be[f0 + 3];
        float c0 = 0.f, c1 = 0.f, c2 = 0.f, c3 = 0.f;
        float k0 = s_bn[f0], k1 = s_bn[f0 + 1], k2 = s_bn[f0 + 2], k3 = s_bn[f0 + 3];
#pragma unroll
        for (int r = 0; r < FIN; r++) {
            float xv = xr[r];
            float4 wd = *reinterpret_cast<const float4*>(&s_wd[r * FOUT + f0]);
            float4 w2 = *reinterpret_cast<const float4*>(&s_w2[r * FOUT + f0]);
            float4 wn = *reinterpret_cast<const float4*>(&s_wn[r * FOUT + f0]);
            a0 = fmaf(xv, wd.x, a0); a1 = fmaf(xv, wd.y, a1);
            a2 = fmaf(xv, wd.z, a2); a3 = fmaf(xv, wd.w, a3);
            c0 = fmaf(xv, w2.x, c0); c1 = fmaf(xv, w2.y, c1);
            c2 = fmaf(xv, w2.z, c2); c3 = fmaf(xv, w2.w, c3);
            k0 = fmaf(xv, wn.x, k0); k1 = fmaf(xv, wn.y, k1);
            k2 = fmaf(xv, wn.z, k2); k3 = fmaf(xv, wn.w, k3);
        }
        size_t o = (size_t)node * FOUT + f0;
        *reinterpret_cast<float4*>(&g_a[o]) = make_float4(a0, a1, a2, a3);
        *reinterpret_cast<float4*>(&g_c[o]) = make_float4(c0, c1, c2, c3);
        *reinterpret_cast<float4*>(&g_s[o]) = make_float4(fmaxf(k0, 0.f), fmaxf(k1, 0.f),
                                                          fmaxf(k2, 0.f), fmaxf(k3, 0.f));
    }
}

// ---------------------------------------------------------------------------
// Kernel 3: aggregation, float4 per thread (4 features).
// out = relu(max_k (a_i + c_{nbr_k})) + s_i
// ---------------------------------------------------------------------------
__global__ __launch_bounds__(256) void aggregate_kernel(float* __restrict__ out) {
    const int gid = blockIdx.x * 256 + threadIdx.x;   // thread per (node, f-quad)
    const int i  = gid >> 4;
    const int f4 = (gid & 15) << 2;

    const int4* r4 = reinterpret_cast<const int4*>(g_idx + (size_t)i * KK);
    int4 j0 = r4[0], j1 = r4[1], j2 = r4[2], j3 = r4[3];
    int jj[KK] = { j0.x, j0.y, j0.z, j0.w, j1.x, j1.y, j1.z, j1.w,
                   j2.x, j2.y, j2.z, j2.w, j3.x, j3.y, j3.z, j3.w };

    float4 m = make_float4(-3.0e38f, -3.0e38f, -3.0e38f, -3.0e38f);
#pragma unroll
    for (int k = 0; k < KK; k++) {
        float4 v = *reinterpret_cast<const float4*>(&g_c[(size_t)jj[k] * FOUT + f4]);
        m.x = fmaxf(m.x, v.x); m.y = fmaxf(m.y, v.y);
        m.z = fmaxf(m.z, v.z); m.w = fmaxf(m.w, v.w);
    }

    const size_t o = (size_t)i * FOUT + f4;
    float4 a = *reinterpret_cast<const float4*>(&g_a[o]);
    float4 s = *reinterpret_cast<const float4*>(&g_s[o]);
    float4 r;
    r.x = fmaxf(m.x + a.x, 0.f) + s.x;
    r.y = fmaxf(m.y + a.y, 0.f) + s.y;
    r.z = fmaxf(m.z + a.z, 0.f) + s.z;
    r.w = fmaxf(m.w + a.w, 0.f) + s.w;
    *reinterpret_cast<float4*>(&out[o]) = r;
}

// ---------------------------------------------------------------------------
extern "C" void kernel_launch(void* const* d_in, const int* in_sizes, int n_in,
                              void* d_out, int out_size) {
    const float* x   = (const float*)d_in[0];
    const float* pos = (const float*)d_in[1];
    const float* We  = (const float*)d_in[2];
    const float* be  = (const float*)d_in[3];
    const float* Wn  = (const float*)d_in[4];
    const float* bn  = (const float*)d_in[5];
    float* out = (float*)d_out;

    sort_kernel<<<BB, 1024>>>(pos);
    knn_kernel<<<BB * 8, 256>>>();
    transform_kernel<<<NPTS / 128, 128>>>(x, We, be, Wn, bn);
    aggregate_kernel<<<(NPTS * FOUT / 4) / 256, 256>>>(out);
}